// round 12
// baseline (speedup 1.0000x reference)
#include <cuda_runtime.h>
#include <cuda_bf16.h>
#include <cstdint>

#define B_   8
#define N_   2048
#define FIN  256
#define FOUT 128
#define ROWS_TOTAL (B_ * N_)   // 16384

// -------- static device scratch --------
__device__ __align__(16) __nv_bfloat16 d_hbf_hi[(size_t)ROWS_TOTAL * FIN];   // 8.4 MB
__device__ __align__(16) __nv_bfloat16 d_hbf_lo[(size_t)ROWS_TOTAL * FIN];
__device__ __align__(16) __nv_bfloat16 d_Wbf_hi[FIN * FOUT];
__device__ __align__(16) __nv_bfloat16 d_Wbf_lo[FIN * FOUT];
__device__ __align__(16) __nv_bfloat16 d_Whbf_hi[(size_t)ROWS_TOTAL * FOUT]; // 4 MB [row][o]
__device__ __align__(16) __nv_bfloat16 d_Whbf_lo[(size_t)ROWS_TOTAL * FOUT];
__device__ float  d_si[ROWS_TOTAL];
__device__ float  d_sj[ROWS_TOTAL];
__device__ __align__(16) float2 d_E12[ROWS_TOTAL];
__device__ __align__(16) float2 d_F12[ROWS_TOTAL];
__device__ unsigned d_smax_bits[B_];   // order-preserving key; atomicMax idempotent across replays

// bf16 pack/split helpers. CVTPK(res,a,b): res = bf16x2 {lo=a, hi=b}
#define CVTPK(res, a, b) \
    asm("cvt.rn.satfinite.bf16x2.f32 %0, %1, %2;" : "=r"(res) : "f"(b), "f"(a))
__device__ __forceinline__ float loF(uint32_t h) { return __uint_as_float(h << 16); }
__device__ __forceinline__ float hiF(uint32_t h) { return __uint_as_float(h & 0xffff0000u); }

__device__ __forceinline__ uint32_t smem_to_u32(const void* p) {
    uint32_t a;
    asm("{ .reg .u64 t; cvta.to.shared.u64 t, %1; cvt.u32.u64 %0, t; }" : "=r"(a) : "l"(p));
    return a;
}
__device__ __forceinline__ void cp16(uint32_t s, const void* g) {
    asm volatile("cp.async.cg.shared.global [%0], [%1], 16;" :: "r"(s), "l"(g) : "memory");
}
#define CP_COMMIT() asm volatile("cp.async.commit_group;" ::: "memory")
#define CP_WAIT(N)  asm volatile("cp.async.wait_group %0;" :: "n"(N) : "memory")

__device__ __forceinline__ void ldsm4(uint32_t* r, uint32_t a) {
    asm volatile("ldmatrix.sync.aligned.m8n8.x4.shared.b16 {%0,%1,%2,%3}, [%4];"
                 : "=r"(r[0]), "=r"(r[1]), "=r"(r[2]), "=r"(r[3]) : "r"(a));
}
__device__ __forceinline__ void ldsm4t(uint32_t* r, uint32_t a) {
    asm volatile("ldmatrix.sync.aligned.m8n8.x4.trans.shared.b16 {%0,%1,%2,%3}, [%4];"
                 : "=r"(r[0]), "=r"(r[1]), "=r"(r[2]), "=r"(r[3]) : "r"(a));
}
__device__ __forceinline__ void mma16816(float* c, const uint32_t* a,
                                         uint32_t b0, uint32_t b1) {
    asm volatile("mma.sync.aligned.m16n8k16.row.col.f32.bf16.bf16.f32 "
                 "{%0,%1,%2,%3}, {%4,%5,%6,%7}, {%8,%9}, {%0,%1,%2,%3};"
                 : "+f"(c[0]), "+f"(c[1]), "+f"(c[2]), "+f"(c[3])
                 : "r"(a[0]), "r"(a[1]), "r"(a[2]), "r"(a[3]), "r"(b0), "r"(b1));
}

// order-preserving float->uint key
__device__ __forceinline__ unsigned fkey(float f) {
    unsigned b = __float_as_uint(f);
    return (b & 0x80000000u) ? ~b : (b | 0x80000000u);
}
__device__ __forceinline__ float funkey(unsigned k) {
    unsigned b = (k & 0x80000000u) ? (k & 0x7fffffffu) : ~k;
    return __uint_as_float(b);
}

// ============================================================================
// Kernel 0: split h and W into bf16 hi/lo (DRAM-bound, ~4.5us)
// ============================================================================
#define NH4 (ROWS_TOTAL * FIN / 4)   // 1048576
#define NW4 (FIN * FOUT / 4)         // 8192
__global__ __launch_bounds__(256) void split_kernel(const float* __restrict__ h,
                                                    const float* __restrict__ W) {
    const int idx = blockIdx.x * 256 + threadIdx.x;
    float4 v;
    __nv_bfloat16 *dhi, *dlo;
    int o4;
    if (idx < NH4) {
        v = ((const float4*)h)[idx];
        dhi = d_hbf_hi; dlo = d_hbf_lo; o4 = idx;
    } else if (idx < NH4 + NW4) {
        v = ((const float4*)W)[idx - NH4];
        dhi = d_Wbf_hi; dlo = d_Wbf_lo; o4 = idx - NH4;
    } else return;
    uint32_t H0, H1;
    CVTPK(H0, v.x, v.y); CVTPK(H1, v.z, v.w);
    float l0 = v.x - loF(H0), l1 = v.y - hiF(H0);
    float l2 = v.z - loF(H1), l3 = v.w - hiF(H1);
    uint32_t L0, L1;
    CVTPK(L0, l0, l1); CVTPK(L1, l2, l3);
    *(uint2*)(dhi + (size_t)o4 * 4) = make_uint2(H0, H1);
    *(uint2*)(dlo + (size_t)o4 * 4) = make_uint2(L0, L1);
}

// ============================================================================
// Kernel A: Wh = h @ W_fc (bf16-split 3-product mma.sync, cp.async staging)
// Block 64i x 128o, 256 thr, 8 warps 4x2 (16i x 64o). K-chunks of 32, 2-buf.
// Epilogue: Whbf hi/lo + s_i/s_j + batch sj-max atomic.
// ============================================================================
#define WAT 80          // A row stride: 64B data + 16 pad
#define WBT 272         // B row stride: 256B data + 16 pad
#define WH_AH  0        // 2 x 5120
#define WH_AL  10240    // 2 x 5120
#define WH_BH  20480    // 2 x 8704
#define WH_BL  37888    // 2 x 8704
#define WH_AIJ 55296    // 1024
#define WH_PSI 56320    // 512
#define WH_PSJ 56832    // 512
#define WH_WMX 57344    // 16
#define SM_TOTAL_WH 57472

__global__ __launch_bounds__(256, 2) void wh_mma_kernel(const float* __restrict__ a_i,
                                                        const float* __restrict__ a_j) {
    extern __shared__ __align__(16) char sm[];
    const uint32_t sm32 = smem_to_u32(sm);
    const int t      = threadIdx.x;
    const int w      = t >> 5;
    const int lane   = t & 31;
    const int wg_row = w >> 1;          // 0..3 -> i base 16*wg_row
    const int wg_col = w & 1;           // 0..1 -> o base 64*wg_col
    const int row0   = blockIdx.x * 64;
    const int b      = row0 >> 11;

    float acc[8][4];
    #pragma unroll
    for (int n = 0; n < 8; n++)
        #pragma unroll
        for (int q = 0; q < 4; q++) acc[n][q] = 0.0f;

    if (t < 128) {
        ((float*)(sm + WH_AIJ))[t]       = a_i[t];
        ((float*)(sm + WH_AIJ))[128 + t] = a_j[t];
    }

    const uint32_t a_base = sm32 + WH_AH + (wg_row * 16 + (lane & 15)) * WAT
                            + ((lane >> 4) << 4);
    const uint32_t b_base = sm32 + WH_BH + (lane & 15) * WBT
                            + ((lane >> 4) << 4) + wg_col * 128;

#define WH_STAGE(CH, S) do { \
        const int _k0 = (CH) * 32; \
        { int i = t >> 2, kq = t & 3; \
          uint32_t ds = (uint32_t)(i * WAT + kq * 16) + (S) * 5120; \
          const size_t gs = (size_t)(row0 + i) * FIN + _k0 + kq * 8; \
          cp16(sm32 + WH_AH + ds, d_hbf_hi + gs); \
          cp16(sm32 + WH_AL + ds, d_hbf_lo + gs); } \
        _Pragma("unroll") \
        for (int m = 0; m < 2; m++) { \
            int idx = t + m * 256; \
            int k = idx >> 4, cq = idx & 15; \
            uint32_t ds = (uint32_t)(k * WBT + cq * 16) + (S) * 8704; \
            const size_t gs = (size_t)(_k0 + k) * FOUT + cq * 8; \
            cp16(sm32 + WH_BH + ds, d_Wbf_hi + gs); \
            cp16(sm32 + WH_BL + ds, d_Wbf_lo + gs); \
        } \
        CP_COMMIT(); \
    } while (0)

    WH_STAGE(0, 0);

    #pragma unroll 1
    for (int c = 0; c < 8; c++) {
        const int s = c & 1;
        __syncthreads();                       // compute(c-1) done -> slot s^1 free
        if (c < 7) WH_STAGE(c + 1, s ^ 1);
        if (c < 7) { CP_WAIT(1); } else { CP_WAIT(0); }
        __syncthreads();                       // chunk c data visible

        const uint32_t ah_b = a_base + s * 5120;
        const uint32_t al_b = ah_b + (WH_AL - WH_AH);
        const uint32_t bh_b = b_base + s * 8704;
        const uint32_t bl_b = bh_b + (WH_BL - WH_BH);
        #pragma unroll
        for (int kc = 0; kc < 2; kc++) {
            uint32_t AH[4], AL[4];
            ldsm4(AH, ah_b + kc * 32);
            ldsm4(AL, al_b + kc * 32);
            const uint32_t bko = kc * 16 * WBT;
            #pragma unroll
            for (int ntp = 0; ntp < 4; ntp++) {
                uint32_t BH[4], BL[4];
                ldsm4t(BH, bh_b + bko + ntp * 32);
                ldsm4t(BL, bl_b + bko + ntp * 32);
                mma16816(acc[2 * ntp],     AH, BH[0], BH[1]);
                mma16816(acc[2 * ntp],     AH, BL[0], BL[1]);
                mma16816(acc[2 * ntp],     AL, BH[0], BH[1]);
                mma16816(acc[2 * ntp + 1], AH, BH[2], BH[3]);
                mma16816(acc[2 * ntp + 1], AH, BL[2], BL[3]);
                mma16816(acc[2 * ntp + 1], AL, BH[2], BH[3]);
            }
        }
    }
#undef WH_STAGE

    // ---- epilogue: bf16 hi/lo store + s_i/s_j partials ----
    const int r0 = wg_row * 16 + (lane >> 2);
    const int r1 = r0 + 8;
    const float* aish = (const float*)(sm + WH_AIJ);
    const float* ajsh = (const float*)(sm + WH_AIJ) + 128;

    float si0 = 0.f, si1 = 0.f, sj0 = 0.f, sj1 = 0.f;
    #pragma unroll
    for (int nt = 0; nt < 8; nt++) {
        const int cc = wg_col * 64 + nt * 8 + (lane & 3) * 2;
        uint32_t Hi0, Hi1;
        CVTPK(Hi0, acc[nt][0], acc[nt][1]);
        CVTPK(Hi1, acc[nt][2], acc[nt][3]);
        float u0 = acc[nt][0] - loF(Hi0), u1 = acc[nt][1] - hiF(Hi0);
        float u2 = acc[nt][2] - loF(Hi1), u3 = acc[nt][3] - hiF(Hi1);
        uint32_t Lo0, Lo1;
        CVTPK(Lo0, u0, u1); CVTPK(Lo1, u2, u3);
        *(uint32_t*)&d_Whbf_hi[(size_t)(row0 + r0) * FOUT + cc] = Hi0;
        *(uint32_t*)&d_Whbf_hi[(size_t)(row0 + r1) * FOUT + cc] = Hi1;
        *(uint32_t*)&d_Whbf_lo[(size_t)(row0 + r0) * FOUT + cc] = Lo0;
        *(uint32_t*)&d_Whbf_lo[(size_t)(row0 + r1) * FOUT + cc] = Lo1;
        float ai0 = aish[cc], ai1 = aish[cc + 1];
        float aj0 = ajsh[cc], aj1 = ajsh[cc + 1];
        si0 += acc[nt][0] * ai0 + acc[nt][1] * ai1;
        sj0 += acc[nt][0] * aj0 + acc[nt][1] * aj1;
        si1 += acc[nt][2] * ai0 + acc[nt][3] * ai1;
        sj1 += acc[nt][2] * aj0 + acc[nt][3] * aj1;
    }
    #pragma unroll
    for (int m = 1; m <= 2; m <<= 1) {
        si0 += __shfl_xor_sync(0xffffffffu, si0, m);
        sj0 += __shfl_xor_sync(0xffffffffu, sj0, m);
        si1 += __shfl_xor_sync(0xffffffffu, si1, m);
        sj1 += __shfl_xor_sync(0xffffffffu, sj1, m);
    }
    if ((lane & 3) == 0) {
        float* psi = (float*)(sm + WH_PSI) + wg_col * 64;
        float* psj = (float*)(sm + WH_PSJ) + wg_col * 64;
        psi[r0] = si0; psi[r1] = si1;
        psj[r0] = sj0; psj[r1] = sj1;
    }
    __syncthreads();
    if (t < 64) {
        const float* psi = (const float*)(sm + WH_PSI);
        const float* psj = (const float*)(sm + WH_PSJ);
        float si = psi[t] + psi[64 + t];
        float sj = psj[t] + psj[64 + t];
        d_si[row0 + t] = si;
        d_sj[row0 + t] = sj;
        float m = sj;
        #pragma unroll
        for (int s = 16; s > 0; s >>= 1)
            m = fmaxf(m, __shfl_xor_sync(0xffffffffu, m, s));
        if (lane == 0) ((float*)(sm + WH_WMX))[w] = m;
    }
    __syncthreads();
    if (t == 0) {
        float m = fmaxf(((float*)(sm + WH_WMX))[0], ((float*)(sm + WH_WMX))[1]);
        atomicMax(&d_smax_bits[b], fkey(m));
    }
}

// ============================================================================
// Kernel B: exp tables
// ============================================================================
__global__ __launch_bounds__(256) void tables_kernel() {
    const int idx = blockIdx.x * 256 + threadIdx.x;
    if (idx >= ROWS_TOTAL) return;
    const int b = idx >> 11;
    const float sm_ = funkey(d_smax_bits[b]);
    const float si = d_si[idx];
    const float sj = d_sj[idx];
    const float tt = si + sm_;
    const float mm = fmaxf(tt, 0.01f * tt);
    d_E12[idx] = make_float2(__expf(tt - mm), __expf(0.01f * tt - mm));
    const float u = sj - sm_;
    d_F12[idx] = make_float2(__expf(u), __expf(0.01f * u));
}

// ============================================================================
// Kernel C: fused h' = softmax(...) @ Wh — 128i x 128o CTA, 512 thr,
// 16 warps 4x4 (32i x 32o warptiles), j-chunks 64, double-buffered A/B.
// ============================================================================
#define AT_STRIDE 144
#define BT_STRIDE 272
#define OFF_F12 0         // 16384
#define OFF_AH  16384     // 2 x 18432
#define OFF_AL  53248     // 2 x 18432
#define OFF_BH  90112     // 2 x 17408
#define OFF_BL  124928    // 2 x 17408
#define OFF_Z   159744    // 2048
#define OFF_RZ  161792    // 512
#define SM_TOTAL_ATTN 162304

__global__ __launch_bounds__(512, 1) void attn_mma_kernel(float* __restrict__ out) {
    extern __shared__ __align__(16) char sm[];
    const uint32_t sm32 = smem_to_u32(sm);
    const int t      = threadIdx.x;
    const int w      = t >> 5;
    const int lane   = t & 31;
    const int wg_row = w >> 2;     // 0..3 -> i base 32*wg_row
    const int wg_col = w & 3;      // 0..3 -> o base 32*wg_col
    const int row0   = blockIdx.x * 128;
    const int b      = row0 >> 11;
    const int i      = t & 127;    // P-gen row
    const int grp    = t >> 7;     // P-gen j-group (16 j each)

    // stage F12 for this batch (16 KB)
    {
        float4* dst = (float4*)(sm + OFF_F12);
        const float4* src = (const float4*)&d_F12[(size_t)b * N_];
        dst[t] = src[t];
        dst[t + 512] = src[t + 512];
    }
    const float2 e = d_E12[row0 + i];
    const float e1 = e.x, e2 = e.y;
    float zacc = 0.0f;
    const float2* fsh = (const float2*)(sm + OFF_F12);

    float acc[2][4][4];
    #pragma unroll
    for (int m = 0; m < 2; m++)
        #pragma unroll
        for (int n = 0; n < 4; n++)
            #pragma unroll
            for (int q = 0; q < 4; q++) acc[m][n][q] = 0.0f;

    const uint32_t a_base = sm32 + OFF_AH + (wg_row * 32 + (lane & 15)) * AT_STRIDE
                            + ((lane >> 4) << 4);
    const uint32_t b_base = sm32 + OFF_BH + (lane & 15) * BT_STRIDE
                            + ((lane >> 4) << 4) + wg_col * 64;

    const __nv_bfloat16* gWhi = &d_Whbf_hi[(size_t)b * N_ * FOUT];
    const __nv_bfloat16* gWlo = &d_Whbf_lo[(size_t)b * N_ * FOUT];

#define STAGE_B(CH, S) do { \
        const int _j0 = (CH) * 64; \
        const uint32_t _bh = sm32 + OFF_BH + (S) * 17408; \
        const uint32_t _bl = sm32 + OFF_BL + (S) * 17408; \
        _Pragma("unroll") \
        for (int m = 0; m < 2; m++) { \
            int idx = t + m * 512; \
            int j = idx >> 4, cq = idx & 15; \
            uint32_t ds = (uint32_t)(j * BT_STRIDE + cq * 16); \
            cp16(_bh + ds, gWhi + (size_t)(_j0 + j) * FOUT + cq * 8); \
            cp16(_bl + ds, gWlo + (size_t)(_j0 + j) * FOUT + cq * 8); \
        } \
        CP_COMMIT(); \
    } while (0)

#define GEN_A(CH, S) do { \
        const int _j0 = (CH) * 64; \
        char* _ah = sm + OFF_AH + (S) * 18432; \
        char* _al = sm + OFF_AL + (S) * 18432; \
        _Pragma("unroll") \
        for (int q = 0; q < 2; q++) { \
            int jl = grp * 16 + q * 8; \
            const float4* fp = (const float4*)&fsh[_j0 + jl]; \
            float4 fa = fp[0], fb = fp[1], fc = fp[2], fd = fp[3]; \
            float p0 = fmaxf(e1 * fa.x, e2 * fa.y); \
            float p1 = fmaxf(e1 * fa.z, e2 * fa.w); \
            float p2 = fmaxf(e1 * fb.x, e2 * fb.y); \
            float p3 = fmaxf(e1 * fb.z, e2 * fb.w); \
            float p4 = fmaxf(e1 * fc.x, e2 * fc.y); \
            float p5 = fmaxf(e1 * fc.z, e2 * fc.w); \
            float p6 = fmaxf(e1 * fd.x, e2 * fd.y); \
            float p7 = fmaxf(e1 * fd.z, e2 * fd.w); \
            zacc += ((p0 + p1) + (p2 + p3)) + ((p4 + p5) + (p6 + p7)); \
            uint32_t h01, h23, h45, h67; \
            CVTPK(h01, p0, p1); CVTPK(h23, p2, p3); \
            CVTPK(h45, p4, p5); CVTPK(h67, p6, p7); \
            float r0_ = p0 - loF(h01), r1_ = p1 - hiF(h01); \
            float r2_ = p2 - loF(h23), r3_ = p3 - hiF(h23); \
            float r4_ = p4 - loF(h45), r5_ = p5 - hiF(h45); \
            float r6_ = p6 - loF(h67), r7_ = p7 - hiF(h67); \
            uint32_t l01, l23, l45, l67; \
            CVTPK(l01, r0_, r1_); CVTPK(l23, r2_, r3_); \
            CVTPK(l45, r4_, r5_); CVTPK(l67, r6_, r7_); \
            uint32_t off = (uint32_t)(i * AT_STRIDE + jl * 2); \
            *(uint4*)(_ah + off) = make_uint4(h01, h23, h45, h67); \
            *(uint4*)(_al + off) = make_uint4(l01, l23, l45, l67); \
        } \
    } while (0)

    __syncthreads();   // F12 visible
    STAGE_B(0, 0);
    GEN_A(0, 0);

    #pragma unroll 1
    for (int c = 0; c < 32; c++) {
        const int s = c & 1;
        __syncthreads();                 // compute(c-1) done -> slot s^1 free; A(c) visible
        if (c < 31) { STAGE_B(c + 1, s ^ 1); GEN_A(c + 1, s ^ 1); }
        if (c < 31) { CP_WAIT(1); } else { CP_WAIT(0); }
        __syncthreads();                 // B(c) visible

        const uint32_t ah_b = a_base + s * 18432;
        const uint32_t al_b = ah_b + (OFF_AL - OFF_AH);
        const uint32_t bh_b = b_base + s * 17408;
        const uint32_t bl_b = bh_b + (OFF_BL - OFF_BH);
        #pragma unroll
        for (int kc = 0; kc < 4; kc++) {
            uint32_t AH[2][4], AL[2][4];
            ldsm4(AH[0], ah_b + kc * 32);
            ldsm4(AH[1], ah_b + 16 * AT_STRIDE + kc * 32);
            ldsm4(AL[0], al_b + kc * 32);
            ldsm4(AL[1], al_b + 16 * AT_STRIDE + kc * 32);
            const uint32_t bko = kc * 16 * BT_STRIDE;
            #pragma unroll
            for (int ntp = 0; ntp < 2; ntp++) {
                uint32_t BH[4], BL[4];
                ldsm4t(BH, bh_b + bko + ntp * 32);
                ldsm4t(BL, bl_b + bko + ntp * 32);
                #pragma unroll
                for (int m = 0; m < 2; m++) {
                    mma16816(acc[m][2 * ntp],     AH[m], BH[0], BH[1]);
                    mma16816(acc[m][2 * ntp],     AH[m], BL[0], BL[1]);
                    mma16816(acc[m][2 * ntp],     AL[m], BH[0], BH[1]);
                    mma16816(acc[m][2 * ntp + 1], AH[m], BH[2], BH[3]);
                    mma16816(acc[m][2 * ntp + 1], AH[m], BL[2], BL[3]);
                    mma16816(acc[m][2 * ntp + 1], AL[m], BH[2], BH[3]);
                }
            }
        }
    }

    // ---- Z reduction (4 grp partials per row) ----
    ((float*)(sm + OFF_Z))[t] = zacc;
    __syncthreads();
    if (t < 128) {
        const float* z = (const float*)(sm + OFF_Z);
        float Z = (z[t] + z[128 + t]) + (z[256 + t] + z[384 + t]);
        ((float*)(sm + OFF_RZ))[t] = 1.0f / Z;
    }
    __syncthreads();

    // ---- epilogue: normalize + store ----
    {
        const float* rzsh = (const float*)(sm + OFF_RZ);
        #pragma unroll
        for (int m = 0; m < 2; m++) {
            const int rl0 = wg_row * 32 + m * 16 + (lane >> 2);
            const int rl1 = rl0 + 8;
            const float rz0 = rzsh[rl0];
            const float rz1 = rzsh[rl1];
            float* o0 = &out[(size_t)(row0 + rl0) * FOUT];
            float* o1 = &out[(size_t)(row0 + rl1) * FOUT];
            #pragma unroll
            for (int n = 0; n < 4; n++) {
                const int cc = wg_col * 32 + n * 8 + (lane & 3) * 2;
                *(float2*)&o0[cc] = make_float2(acc[m][n][0] * rz0, acc[m][n][1] * rz0);
                *(float2*)&o1[cc] = make_float2(acc[m][n][2] * rz1, acc[m][n][3] * rz1);
            }
        }
    }
#undef STAGE_B
#undef GEN_A
}

// ============================================================================
// launch
// ============================================================================
extern "C" void kernel_launch(void* const* d_in, const int* in_sizes, int n_in,
                              void* d_out, int out_size) {
    const float* h    = (const float*)d_in[0];  // [8,2048,256]
    const float* W_fc = (const float*)d_in[1];  // [256,128]
    const float* a_i  = (const float*)d_in[2];  // [128]
    const float* a_j  = (const float*)d_in[3];  // [128]
    float* out = (float*)d_out;                 // [8,2048,128]

    cudaFuncSetAttribute(wh_mma_kernel,
                         cudaFuncAttributeMaxDynamicSharedMemorySize, SM_TOTAL_WH);
    cudaFuncSetAttribute(attn_mma_kernel,
                         cudaFuncAttributeMaxDynamicSharedMemorySize, SM_TOTAL_ATTN);

    split_kernel<<<(NH4 + NW4 + 255) / 256, 256>>>(h, W_fc);
    wh_mma_kernel<<<ROWS_TOTAL / 64, 256, SM_TOTAL_WH>>>(a_i, a_j);
    tables_kernel<<<ROWS_TOTAL / 256, 256>>>();
    attn_mma_kernel<<<ROWS_TOTAL / 128, 512, SM_TOTAL_ATTN>>>(out);
}

// round 17
// speedup vs baseline: 1.0693x; 1.0693x over previous
#include <cuda_runtime.h>
#include <cuda_bf16.h>
#include <cstdint>

#define B_   8
#define N_   2048
#define FIN  256
#define FOUT 128
#define ROWS_TOTAL (B_ * N_)   // 16384

// -------- static device scratch --------
__device__ __align__(16) __nv_bfloat16 d_hbf_hi[(size_t)ROWS_TOTAL * FIN];   // 8.4 MB
__device__ __align__(16) __nv_bfloat16 d_hbf_lo[(size_t)ROWS_TOTAL * FIN];
__device__ __align__(16) __nv_bfloat16 d_Wbf_hi[FIN * FOUT];
__device__ __align__(16) __nv_bfloat16 d_Wbf_lo[FIN * FOUT];
__device__ __align__(16) __nv_bfloat16 d_Whbf_hi[(size_t)ROWS_TOTAL * FOUT]; // 4 MB [row][o]
__device__ __align__(16) __nv_bfloat16 d_Whbf_lo[(size_t)ROWS_TOTAL * FOUT];
__device__ float  d_si[ROWS_TOTAL];
__device__ float  d_sj[ROWS_TOTAL];
__device__ __align__(16) float2 d_E12[ROWS_TOTAL];
__device__ __align__(16) float2 d_F12[ROWS_TOTAL];
__device__ unsigned d_smax_bits[B_];   // order-preserving key; atomicMax idempotent across replays

// bf16 pack/split helpers. CVTPK(res,a,b): res = bf16x2 {lo=a, hi=b}
#define CVTPK(res, a, b) \
    asm("cvt.rn.satfinite.bf16x2.f32 %0, %1, %2;" : "=r"(res) : "f"(b), "f"(a))
__device__ __forceinline__ float loF(uint32_t h) { return __uint_as_float(h << 16); }
__device__ __forceinline__ float hiF(uint32_t h) { return __uint_as_float(h & 0xffff0000u); }

__device__ __forceinline__ uint32_t smem_to_u32(const void* p) {
    uint32_t a;
    asm("{ .reg .u64 t; cvta.to.shared.u64 t, %1; cvt.u32.u64 %0, t; }" : "=r"(a) : "l"(p));
    return a;
}
__device__ __forceinline__ void cp16(uint32_t s, const void* g) {
    asm volatile("cp.async.cg.shared.global [%0], [%1], 16;" :: "r"(s), "l"(g) : "memory");
}
#define CP_COMMIT() asm volatile("cp.async.commit_group;" ::: "memory")
#define CP_WAIT(N)  asm volatile("cp.async.wait_group %0;" :: "n"(N) : "memory")

__device__ __forceinline__ void ldsm4(uint32_t* r, uint32_t a) {
    asm volatile("ldmatrix.sync.aligned.m8n8.x4.shared.b16 {%0,%1,%2,%3}, [%4];"
                 : "=r"(r[0]), "=r"(r[1]), "=r"(r[2]), "=r"(r[3]) : "r"(a));
}
__device__ __forceinline__ void ldsm4t(uint32_t* r, uint32_t a) {
    asm volatile("ldmatrix.sync.aligned.m8n8.x4.trans.shared.b16 {%0,%1,%2,%3}, [%4];"
                 : "=r"(r[0]), "=r"(r[1]), "=r"(r[2]), "=r"(r[3]) : "r"(a));
}
__device__ __forceinline__ void mma16816(float* c, const uint32_t* a,
                                         uint32_t b0, uint32_t b1) {
    asm volatile("mma.sync.aligned.m16n8k16.row.col.f32.bf16.bf16.f32 "
                 "{%0,%1,%2,%3}, {%4,%5,%6,%7}, {%8,%9}, {%0,%1,%2,%3};"
                 : "+f"(c[0]), "+f"(c[1]), "+f"(c[2]), "+f"(c[3])
                 : "r"(a[0]), "r"(a[1]), "r"(a[2]), "r"(a[3]), "r"(b0), "r"(b1));
}

// order-preserving float->uint key
__device__ __forceinline__ unsigned fkey(float f) {
    unsigned b = __float_as_uint(f);
    return (b & 0x80000000u) ? ~b : (b | 0x80000000u);
}
__device__ __forceinline__ float funkey(unsigned k) {
    unsigned b = (k & 0x80000000u) ? (k & 0x7fffffffu) : ~k;
    return __uint_as_float(b);
}

// ============================================================================
// Kernel 0: split h and W into bf16 hi/lo (DRAM-bound, ~4.5us)
// ============================================================================
#define NH4 (ROWS_TOTAL * FIN / 4)   // 1048576
#define NW4 (FIN * FOUT / 4)         // 8192
__global__ __launch_bounds__(256) void split_kernel(const float* __restrict__ h,
                                                    const float* __restrict__ W) {
    const int idx = blockIdx.x * 256 + threadIdx.x;
    float4 v;
    __nv_bfloat16 *dhi, *dlo;
    int o4;
    if (idx < NH4) {
        v = ((const float4*)h)[idx];
        dhi = d_hbf_hi; dlo = d_hbf_lo; o4 = idx;
    } else if (idx < NH4 + NW4) {
        v = ((const float4*)W)[idx - NH4];
        dhi = d_Wbf_hi; dlo = d_Wbf_lo; o4 = idx - NH4;
    } else return;
    uint32_t H0, H1;
    CVTPK(H0, v.x, v.y); CVTPK(H1, v.z, v.w);
    float l0 = v.x - loF(H0), l1 = v.y - hiF(H0);
    float l2 = v.z - loF(H1), l3 = v.w - hiF(H1);
    uint32_t L0, L1;
    CVTPK(L0, l0, l1); CVTPK(L1, l2, l3);
    *(uint2*)(dhi + (size_t)o4 * 4) = make_uint2(H0, H1);
    *(uint2*)(dlo + (size_t)o4 * 4) = make_uint2(L0, L1);
}

// ============================================================================
// Kernel A: Wh = h @ W_fc (bf16-split 3-product mma.sync, cp.async staging)
// Block 64i x 128o, 256 thr, 8 warps 4x2 (16i x 64o). K-chunks of 32, 2-buf.
// Epilogue: Whbf hi/lo + s_i/s_j + batch sj-max atomic.
// ============================================================================
#define WAT 80          // A row stride: 64B data + 16 pad
#define WBT 272         // B row stride: 256B data + 16 pad
#define WH_AH  0        // 2 x 5120
#define WH_AL  10240    // 2 x 5120
#define WH_BH  20480    // 2 x 8704
#define WH_BL  37888    // 2 x 8704
#define WH_AIJ 55296    // 1024
#define WH_PSI 56320    // 512
#define WH_PSJ 56832    // 512
#define WH_WMX 57344    // 16
#define SM_TOTAL_WH 57472

__global__ __launch_bounds__(256, 2) void wh_mma_kernel(const float* __restrict__ a_i,
                                                        const float* __restrict__ a_j) {
    extern __shared__ __align__(16) char sm[];
    const uint32_t sm32 = smem_to_u32(sm);
    const int t      = threadIdx.x;
    const int w      = t >> 5;
    const int lane   = t & 31;
    const int wg_row = w >> 1;          // 0..3 -> i base 16*wg_row
    const int wg_col = w & 1;           // 0..1 -> o base 64*wg_col
    const int row0   = blockIdx.x * 64;
    const int b      = row0 >> 11;

    float acc[8][4];
    #pragma unroll
    for (int n = 0; n < 8; n++)
        #pragma unroll
        for (int q = 0; q < 4; q++) acc[n][q] = 0.0f;

    if (t < 128) {
        ((float*)(sm + WH_AIJ))[t]       = a_i[t];
        ((float*)(sm + WH_AIJ))[128 + t] = a_j[t];
    }

    const uint32_t a_base = sm32 + WH_AH + (wg_row * 16 + (lane & 15)) * WAT
                            + ((lane >> 4) << 4);
    const uint32_t b_base = sm32 + WH_BH + (lane & 15) * WBT
                            + ((lane >> 4) << 4) + wg_col * 128;

#define WH_STAGE(CH, S) do { \
        const int _k0 = (CH) * 32; \
        { int i = t >> 2, kq = t & 3; \
          uint32_t ds = (uint32_t)(i * WAT + kq * 16) + (S) * 5120; \
          const size_t gs = (size_t)(row0 + i) * FIN + _k0 + kq * 8; \
          cp16(sm32 + WH_AH + ds, d_hbf_hi + gs); \
          cp16(sm32 + WH_AL + ds, d_hbf_lo + gs); } \
        _Pragma("unroll") \
        for (int m = 0; m < 2; m++) { \
            int idx = t + m * 256; \
            int k = idx >> 4, cq = idx & 15; \
            uint32_t ds = (uint32_t)(k * WBT + cq * 16) + (S) * 8704; \
            const size_t gs = (size_t)(_k0 + k) * FOUT + cq * 8; \
            cp16(sm32 + WH_BH + ds, d_Wbf_hi + gs); \
            cp16(sm32 + WH_BL + ds, d_Wbf_lo + gs); \
        } \
        CP_COMMIT(); \
    } while (0)

    WH_STAGE(0, 0);

    #pragma unroll 1
    for (int c = 0; c < 8; c++) {
        const int s = c & 1;
        __syncthreads();                       // compute(c-1) done -> slot s^1 free
        if (c < 7) WH_STAGE(c + 1, s ^ 1);
        if (c < 7) { CP_WAIT(1); } else { CP_WAIT(0); }
        __syncthreads();                       // chunk c data visible

        const uint32_t ah_b = a_base + s * 5120;
        const uint32_t al_b = ah_b + (WH_AL - WH_AH);
        const uint32_t bh_b = b_base + s * 8704;
        const uint32_t bl_b = bh_b + (WH_BL - WH_BH);
        #pragma unroll
        for (int kc = 0; kc < 2; kc++) {
            uint32_t AH[4], AL[4];
            ldsm4(AH, ah_b + kc * 32);
            ldsm4(AL, al_b + kc * 32);
            const uint32_t bko = kc * 16 * WBT;
            #pragma unroll
            for (int ntp = 0; ntp < 4; ntp++) {
                uint32_t BH[4], BL[4];
                ldsm4t(BH, bh_b + bko + ntp * 32);
                ldsm4t(BL, bl_b + bko + ntp * 32);
                mma16816(acc[2 * ntp],     AH, BH[0], BH[1]);
                mma16816(acc[2 * ntp],     AH, BL[0], BL[1]);
                mma16816(acc[2 * ntp],     AL, BH[0], BH[1]);
                mma16816(acc[2 * ntp + 1], AH, BH[2], BH[3]);
                mma16816(acc[2 * ntp + 1], AH, BL[2], BL[3]);
                mma16816(acc[2 * ntp + 1], AL, BH[2], BH[3]);
            }
        }
    }
#undef WH_STAGE

    // ---- epilogue: bf16 hi/lo store + s_i/s_j partials ----
    const int r0 = wg_row * 16 + (lane >> 2);
    const int r1 = r0 + 8;
    const float* aish = (const float*)(sm + WH_AIJ);
    const float* ajsh = (const float*)(sm + WH_AIJ) + 128;

    float si0 = 0.f, si1 = 0.f, sj0 = 0.f, sj1 = 0.f;
    #pragma unroll
    for (int nt = 0; nt < 8; nt++) {
        const int cc = wg_col * 64 + nt * 8 + (lane & 3) * 2;
        uint32_t Hi0, Hi1;
        CVTPK(Hi0, acc[nt][0], acc[nt][1]);
        CVTPK(Hi1, acc[nt][2], acc[nt][3]);
        float u0 = acc[nt][0] - loF(Hi0), u1 = acc[nt][1] - hiF(Hi0);
        float u2 = acc[nt][2] - loF(Hi1), u3 = acc[nt][3] - hiF(Hi1);
        uint32_t Lo0, Lo1;
        CVTPK(Lo0, u0, u1); CVTPK(Lo1, u2, u3);
        *(uint32_t*)&d_Whbf_hi[(size_t)(row0 + r0) * FOUT + cc] = Hi0;
        *(uint32_t*)&d_Whbf_hi[(size_t)(row0 + r1) * FOUT + cc] = Hi1;
        *(uint32_t*)&d_Whbf_lo[(size_t)(row0 + r0) * FOUT + cc] = Lo0;
        *(uint32_t*)&d_Whbf_lo[(size_t)(row0 + r1) * FOUT + cc] = Lo1;
        float ai0 = aish[cc], ai1 = aish[cc + 1];
        float aj0 = ajsh[cc], aj1 = ajsh[cc + 1];
        si0 += acc[nt][0] * ai0 + acc[nt][1] * ai1;
        sj0 += acc[nt][0] * aj0 + acc[nt][1] * aj1;
        si1 += acc[nt][2] * ai0 + acc[nt][3] * ai1;
        sj1 += acc[nt][2] * aj0 + acc[nt][3] * aj1;
    }
    #pragma unroll
    for (int m = 1; m <= 2; m <<= 1) {
        si0 += __shfl_xor_sync(0xffffffffu, si0, m);
        sj0 += __shfl_xor_sync(0xffffffffu, sj0, m);
        si1 += __shfl_xor_sync(0xffffffffu, si1, m);
        sj1 += __shfl_xor_sync(0xffffffffu, sj1, m);
    }
    if ((lane & 3) == 0) {
        float* psi = (float*)(sm + WH_PSI) + wg_col * 64;
        float* psj = (float*)(sm + WH_PSJ) + wg_col * 64;
        psi[r0] = si0; psi[r1] = si1;
        psj[r0] = sj0; psj[r1] = sj1;
    }
    __syncthreads();
    if (t < 64) {
        const float* psi = (const float*)(sm + WH_PSI);
        const float* psj = (const float*)(sm + WH_PSJ);
        float si = psi[t] + psi[64 + t];
        float sj = psj[t] + psj[64 + t];
        d_si[row0 + t] = si;
        d_sj[row0 + t] = sj;
        float m = sj;
        #pragma unroll
        for (int s = 16; s > 0; s >>= 1)
            m = fmaxf(m, __shfl_xor_sync(0xffffffffu, m, s));
        if (lane == 0) ((float*)(sm + WH_WMX))[w] = m;
    }
    __syncthreads();
    if (t == 0) {
        float m = fmaxf(((float*)(sm + WH_WMX))[0], ((float*)(sm + WH_WMX))[1]);
        atomicMax(&d_smax_bits[b], fkey(m));
    }
}

// ============================================================================
// Kernel B: exp tables
// ============================================================================
__global__ __launch_bounds__(256) void tables_kernel() {
    const int idx = blockIdx.x * 256 + threadIdx.x;
    if (idx >= ROWS_TOTAL) return;
    const int b = idx >> 11;
    const float sm_ = funkey(d_smax_bits[b]);
    const float si = d_si[idx];
    const float sj = d_sj[idx];
    const float tt = si + sm_;
    const float mm = fmaxf(tt, 0.01f * tt);
    d_E12[idx] = make_float2(__expf(tt - mm), __expf(0.01f * tt - mm));
    const float u = sj - sm_;
    d_F12[idx] = make_float2(__expf(u), __expf(0.01f * u));
}

// ============================================================================
// Kernel C: fused h' = softmax(...) @ Wh — 128i x 128o CTA, 512 thr,
// 16 warps 4x4 (32i x 32o warptiles). j-chunks 64, THREE-stage ring,
// ONE __syncthreads per chunk; compute issued before next-stage staging so
// GEN_A/cp.async drain under the tensor-pipe shadow. F12 read from gmem
// (warp-uniform, L2-hot).
// ============================================================================
#define AT_STRIDE 144
#define BT_STRIDE 272
#define ASLOT 18432
#define BSLOT 17408
#define OFF_AH  0                      // 3 x 18432 = 55296
#define OFF_AL  55296                  // 3 x 18432 = 55296
#define OFF_BH  110592                 // 3 x 17408 = 52224
#define OFF_BL  162816                 // 3 x 17408 = 52224
#define OFF_Z   215040                 // 2048
#define OFF_RZ  217088                 // 512
#define SM_TOTAL_ATTN 217600

__global__ __launch_bounds__(512, 1) void attn_mma_kernel(float* __restrict__ out) {
    extern __shared__ __align__(16) char sm[];
    const uint32_t sm32 = smem_to_u32(sm);
    const int t      = threadIdx.x;
    const int w      = t >> 5;
    const int lane   = t & 31;
    const int wg_row = w >> 2;     // 0..3 -> i base 32*wg_row
    const int wg_col = w & 3;      // 0..3 -> o base 32*wg_col
    const int row0   = blockIdx.x * 128;
    const int b      = row0 >> 11;
    const int i      = t & 127;    // P-gen row
    const int grp    = t >> 7;     // P-gen j-group (16 j each) — uniform per warp

    const float2 e = d_E12[row0 + i];
    const float e1 = e.x, e2 = e.y;
    float zacc = 0.0f;
    const float2* gF = &d_F12[(size_t)b * N_];

    float acc[2][4][4];
    #pragma unroll
    for (int m = 0; m < 2; m++)
        #pragma unroll
        for (int n = 0; n < 4; n++)
            #pragma unroll
            for (int q = 0; q < 4; q++) acc[m][n][q] = 0.0f;

    const uint32_t a_base = sm32 + OFF_AH + (wg_row * 32 + (lane & 15)) * AT_STRIDE
                            + ((lane >> 4) << 4);
    const uint32_t b_base = sm32 + OFF_BH + (lane & 15) * BT_STRIDE
                            + ((lane >> 4) << 4) + wg_col * 64;

    const __nv_bfloat16* gWhi = &d_Whbf_hi[(size_t)b * N_ * FOUT];
    const __nv_bfloat16* gWlo = &d_Whbf_lo[(size_t)b * N_ * FOUT];

#define STAGE_B(CH, S) do { \
        const int _j0 = (CH) * 64; \
        const uint32_t _bh = sm32 + OFF_BH + (S) * BSLOT; \
        const uint32_t _bl = sm32 + OFF_BL + (S) * BSLOT; \
        _Pragma("unroll") \
        for (int m = 0; m < 2; m++) { \
            int idx = t + m * 512; \
            int j = idx >> 4, cq = idx & 15; \
            uint32_t ds = (uint32_t)(j * BT_STRIDE + cq * 16); \
            cp16(_bh + ds, gWhi + (size_t)(_j0 + j) * FOUT + cq * 8); \
            cp16(_bl + ds, gWlo + (size_t)(_j0 + j) * FOUT + cq * 8); \
        } \
        CP_COMMIT(); \
    } while (0)

#define GEN_A(CH, S) do { \
        const int _j0 = (CH) * 64; \
        char* _ah = sm + OFF_AH + (S) * ASLOT; \
        char* _al = sm + OFF_AL + (S) * ASLOT; \
        _Pragma("unroll") \
        for (int q = 0; q < 2; q++) { \
            int jl = grp * 16 + q * 8; \
            const float4* fp = (const float4*)&gF[_j0 + jl]; \
            float4 fa = fp[0], fb = fp[1], fc = fp[2], fd = fp[3]; \
            float p0 = fmaxf(e1 * fa.x, e2 * fa.y); \
            float p1 = fmaxf(e1 * fa.z, e2 * fa.w); \
            float p2 = fmaxf(e1 * fb.x, e2 * fb.y); \
            float p3 = fmaxf(e1 * fb.z, e2 * fb.w); \
            float p4 = fmaxf(e1 * fc.x, e2 * fc.y); \
            float p5 = fmaxf(e1 * fc.z, e2 * fc.w); \
            float p6 = fmaxf(e1 * fd.x, e2 * fd.y); \
            float p7 = fmaxf(e1 * fd.z, e2 * fd.w); \
            zacc += ((p0 + p1) + (p2 + p3)) + ((p4 + p5) + (p6 + p7)); \
            uint32_t h01, h23, h45, h67; \
            CVTPK(h01, p0, p1); CVTPK(h23, p2, p3); \
            CVTPK(h45, p4, p5); CVTPK(h67, p6, p7); \
            float r0_ = p0 - loF(h01), r1_ = p1 - hiF(h01); \
            float r2_ = p2 - loF(h23), r3_ = p3 - hiF(h23); \
            float r4_ = p4 - loF(h45), r5_ = p5 - hiF(h45); \
            float r6_ = p6 - loF(h67), r7_ = p7 - hiF(h67); \
            uint32_t l01, l23, l45, l67; \
            CVTPK(l01, r0_, r1_); CVTPK(l23, r2_, r3_); \
            CVTPK(l45, r4_, r5_); CVTPK(l67, r6_, r7_); \
            uint32_t off = (uint32_t)(i * AT_STRIDE + jl * 2); \
            *(uint4*)(_ah + off) = make_uint4(h01, h23, h45, h67); \
            *(uint4*)(_al + off) = make_uint4(l01, l23, l45, l67); \
        } \
    } while (0)

    // prologue: fill two stages
    STAGE_B(0, 0); GEN_A(0, 0);
    STAGE_B(1, 1); GEN_A(1, 1);

    #pragma unroll 1
    for (int c = 0; c < 32; c++) {
        const int s = c - (c / 3) * 3;          // c % 3
        CP_WAIT(1);                 // B(c) landed (this thread's groups)
        __syncthreads();            // all warps done compute(c-1); A(c)/B(c) visible

        const uint32_t ah_b = a_base + s * ASLOT;
        const uint32_t al_b = ah_b + (OFF_AL - OFF_AH);
        const uint32_t bh_b = b_base + s * BSLOT;
        const uint32_t bl_b = bh_b + (OFF_BL - OFF_BH);
        #pragma unroll
        for (int kc = 0; kc < 4; kc++) {
            uint32_t AH[2][4], AL[2][4];
            ldsm4(AH[0], ah_b + kc * 32);
            ldsm4(AH[1], ah_b + 16 * AT_STRIDE + kc * 32);
            ldsm4(AL[0], al_b + kc * 32);
            ldsm4(AL[1], al_b + 16 * AT_STRIDE + kc * 32);
            const uint32_t bko = kc * 16 * BT_STRIDE;
            #pragma unroll
            for (int ntp = 0; ntp < 2; ntp++) {
                uint32_t BH[4], BL[4];
                ldsm4t(BH, bh_b + bko + ntp * 32);
                ldsm4t(BL, bl_b + bko + ntp * 32);
                #pragma unroll
                for (int m = 0; m < 2; m++) {
                    mma16816(acc[m][2 * ntp],     AH[m], BH[0], BH[1]);
                    mma16816(acc[m][2 * ntp],     AH[m], BL[0], BL[1]);
                    mma16816(acc[m][2 * ntp],     AL[m], BH[0], BH[1]);
                    mma16816(acc[m][2 * ntp + 1], AH[m], BH[2], BH[3]);
                    mma16816(acc[m][2 * ntp + 1], AH[m], BL[2], BL[3]);
                    mma16816(acc[m][2 * ntp + 1], AL[m], BH[2], BH[3]);
                }
            }
        }

        // stage chunk c+2 into slot (c+2)%3 == (c-1)%3 — its readers (chunk
        // c-1) finished before this iteration's barrier. Issued AFTER the
        // HMMAs so ALU/LSU work drains while the tensor pipe is busy.
        if (c + 2 < 32) {
            const int s2 = (c + 2) - ((c + 2) / 3) * 3;
            STAGE_B(c + 2, s2);
            GEN_A(c + 2, s2);
        }
    }

    // ---- Z reduction (4 grp partials per row) ----
    ((float*)(sm + OFF_Z))[t] = zacc;
    __syncthreads();
    if (t < 128) {
        const float* z = (const float*)(sm + OFF_Z);
        float Z = (z[t] + z[128 + t]) + (z[256 + t] + z[384 + t]);
        ((float*)(sm + OFF_RZ))[t] = 1.0f / Z;
    }
    __syncthreads();

    // ---- epilogue: normalize + store ----
    {
        const float* rzsh = (const float*)(sm + OFF_RZ);
        #pragma unroll
        for (int m = 0; m < 2; m++) {
            const int rl0 = wg_row * 32 + m * 16 + (lane >> 2);
            const int rl1 = rl0 + 8;
            const float rz0 = rzsh[rl0];
            const float rz1 = rzsh[rl1];
            float* o0 = &out[(size_t)(row0 + rl0) * FOUT];
            float* o1 = &out[(size_t)(row0 + rl1) * FOUT];
            #pragma unroll
            for (int n = 0; n < 4; n++) {
                const int cc = wg_col * 32 + n * 8 + (lane & 3) * 2;
                *(float2*)&o0[cc] = make_float2(acc[m][n][0] * rz0, acc[m][n][1] * rz0);
                *(float2*)&o1[cc] = make_float2(acc[m][n][2] * rz1, acc[m][n][3] * rz1);
            }
        }
    }
#undef STAGE_B
#undef GEN_A
}

// ============================================================================
// launch
// ============================================================================
extern "C" void kernel_launch(void* const* d_in, const int* in_sizes, int n_in,
                              void* d_out, int out_size) {
    const float* h    = (const float*)d_in[0];  // [8,2048,256]
    const float* W_fc = (const float*)d_in[1];  // [256,128]
    const float* a_i  = (const float*)d_in[2];  // [128]
    const float* a_j  = (const float*)d_in[3];  // [128]
    float* out = (float*)d_out;                 // [8,2048,128]

    cudaFuncSetAttribute(wh_mma_kernel,
                         cudaFuncAttributeMaxDynamicSharedMemorySize, SM_TOTAL_WH);
    cudaFuncSetAttribute(attn_mma_kernel,
                         cudaFuncAttributeMaxDynamicSharedMemorySize, SM_TOTAL_ATTN);

    split_kernel<<<(NH4 + NW4 + 255) / 256, 256>>>(h, W_fc);
    wh_mma_kernel<<<ROWS_TOTAL / 64, 256, SM_TOTAL_WH>>>(a_i, a_j);
    tables_kernel<<<ROWS_TOTAL / 256, 256>>>();
    attn_mma_kernel<<<ROWS_TOTAL / 128, 512, SM_TOTAL_ATTN>>>(out);
}